// round 14
// baseline (speedup 1.0000x reference)
#include <cuda_runtime.h>
#include <cuda_fp16.h>
#include <cstdint>
#include <cstddef>

// ---------------------------------------------------------------------------
// Problem constants
// ---------------------------------------------------------------------------
#define BROWS  32768
#define DMODEL 1024
#define NHEADS 16
#define HDIM   64

// Scratch (__device__ globals = allocation-guard-safe)
#define SLOT_ELEMS 33554432ull                  // B*D elements
__device__ float g_pool[11ull * SLOT_ELEMS];
#define DD 1048576ull
__device__ float g_wr[5ull * DD + 10240];

// fp16 region offsets (halves, from hbase = (half*)g_pool)
#define OFF_ZT   0ull
#define OFF_ZVA  33554432ull     // 32Mi
#define OFF_QOUT 100663296ull    // 96Mi
#define OFF_KV   167772160ull    // 160Mi  (65536 x 4096)
#define OFF_AOC  436207616ull    // 416Mi
#define OFF_AOF  469762048ull    // 448Mi (contiguous after AOC)
#define OFF_C    503316480ull    // 480Mi
#define OFF_LN   570425344ull    // 544Mi

// ---------------------------------------------------------------------------
// Helpers
// ---------------------------------------------------------------------------
__device__ __forceinline__ float gelu_exact(float x) {
    return 0.5f * x * (1.0f + erff(x * 0.70710678118654752440f));
}

// Packed-A layout v2 (R11): chunk (mtile of 128 rows, kb of 32 cols) = 8KB.
// line L = r>>1 holds rows 2L,2L+1 (128B); 16B granules XOR-swizzled by (L&3)
// within each 64B half. ldmatrix-conflict-free AND dense writer rows.
__device__ __forceinline__ size_t packA_idx_h(uint32_t row, uint32_t col) {
    uint32_t mtile = row >> 7, r = row & 127;
    uint32_t kb = col >> 5, c = col & 31;
    uint32_t L = r >> 1;
    uint32_t b = (r & 1) * 64 + c * 2;
    uint32_t g = b >> 4;
    uint32_t gp = (g & 4) | ((g & 3) ^ (L & 3));
    uint32_t byte = L * 128 + gp * 16 + (b & 15);
    return (((size_t)(mtile * 32 + kb)) << 12) + (byte >> 1);
}

// ---------------------------------------------------------------------------
// Fused pack kernels (smem-staged, coalesced)
// ---------------------------------------------------------------------------
struct PackASrcs { const float* src[3]; };   // handled per 8192-chunk region
struct PackWSrcs { const float* src[10]; };  // one DD (1024x1024) weight each

// pack_a_all: grid 24576; region = blockIdx.x >> 13 (0:Z_V, 1:Z_A, 2:Z_T)
__global__ __launch_bounds__(256) void pack_a_all(PackASrcs ps, __half* __restrict__ dstZVA,
                                                  __half* __restrict__ dstZT) {
    __shared__ float sm[128][34];
    uint32_t bid = blockIdx.x;
    uint32_t region = bid >> 13;           // 0,1,2
    uint32_t chunk = bid & 8191;
    const float* src = ps.src[region];
    __half* dst = (region == 2) ? dstZT : dstZVA + (size_t)region * SLOT_ELEMS;

    uint32_t mtile = chunk >> 5, kb = chunk & 31;
    const float* base = src + (size_t)mtile * 131072 + kb * 32;
    int t = threadIdx.x;
    int r0 = t >> 3, c4 = (t & 7) * 4;
#pragma unroll
    for (int i = 0; i < 4; ++i) {
        int r = r0 + i * 32;
        float4 v = *(const float4*)(base + (size_t)r * 1024 + c4);
        sm[r][c4] = v.x; sm[r][c4 + 1] = v.y; sm[r][c4 + 2] = v.z; sm[r][c4 + 3] = v.w;
    }
    __syncthreads();
    uint4* out = (uint4*)dst + ((size_t)chunk << 9);
#pragma unroll
    for (int j = 0; j < 2; ++j) {
        int G = t * 2 + j;
        int L = G >> 3, gp = G & 7;
        int g = (gp & 4) | ((gp & 3) ^ (L & 3));
        int b = g * 16;
        int r = 2 * L + (b >= 64 ? 1 : 0);
        int c0 = (b & 63) >> 1;
        __half2 h0 = __floats2half2_rn(sm[r][c0],     sm[r][c0 + 1]);
        __half2 h1 = __floats2half2_rn(sm[r][c0 + 2], sm[r][c0 + 3]);
        __half2 h2 = __floats2half2_rn(sm[r][c0 + 4], sm[r][c0 + 5]);
        __half2 h3 = __floats2half2_rn(sm[r][c0 + 6], sm[r][c0 + 7]);
        uint4 o;
        o.x = *(uint32_t*)&h0; o.y = *(uint32_t*)&h1;
        o.z = *(uint32_t*)&h2; o.w = *(uint32_t*)&h3;
        out[G] = o;
    }
}

// pack_w_all: grid 2560; weight index = blockIdx.x >> 8, chunk = blockIdx.x & 255.
// dst = wh + widx*DD (fragment-major; B path uses LDS.128).
__global__ __launch_bounds__(256) void pack_w_all(PackWSrcs ps, __half* __restrict__ wh) {
    __shared__ float sm[128][34];
    uint32_t bid = blockIdx.x;
    uint32_t widx = bid >> 8;
    uint32_t chunk = bid & 255;
    const float* src = ps.src[widx];
    __half* dst = wh + (size_t)widx * DD;

    uint32_t ntile = chunk >> 5, kb = chunk & 31;
    const float* base = src + (size_t)ntile * 131072 + kb * 32;
    int t = threadIdx.x;
    int r0 = t >> 3, c4 = (t & 7) * 4;
#pragma unroll
    for (int i = 0; i < 4; ++i) {
        int r = r0 + i * 32;
        float4 v = *(const float4*)(base + (size_t)r * 1024 + c4);
        sm[r][c4] = v.x; sm[r][c4 + 1] = v.y; sm[r][c4 + 2] = v.z; sm[r][c4 + 3] = v.w;
    }
    __syncthreads();
    uint4* out = (uint4*)dst + ((size_t)chunk << 9);
#pragma unroll
    for (int i = 0; i < 2; ++i) {
        int w = t + i * 256;
        int lane = w & 31, p = (w >> 5) & 1, ks = (w >> 6) & 1, wn = (w >> 7) & 3;
        int g = lane >> 2, tig = lane & 3;
        int n0 = wn * 32 + p * 16 + g;
        int k0 = ks * 16 + tig * 2;
        __half2 h0 = __floats2half2_rn(sm[n0][k0],         sm[n0][k0 + 1]);
        __half2 h1 = __floats2half2_rn(sm[n0][k0 + 8],     sm[n0][k0 + 9]);
        __half2 h2 = __floats2half2_rn(sm[n0 + 8][k0],     sm[n0 + 8][k0 + 1]);
        __half2 h3 = __floats2half2_rn(sm[n0 + 8][k0 + 8], sm[n0 + 8][k0 + 9]);
        uint4 o;
        o.x = *(uint32_t*)&h0; o.y = *(uint32_t*)&h1;
        o.z = *(uint32_t*)&h2; o.w = *(uint32_t*)&h3;
        out[w] = o;
    }
}

// Concatenated bias vectors
__global__ void build_bias(const float* __restrict__ bqkv_cons, const float* __restrict__ bqkv_conf,
                           const float* __restrict__ bo_cons, const float* __restrict__ bo_conf,
                           const float* __restrict__ bp_cons, const float* __restrict__ bp_conf,
                           float* __restrict__ biasQ, float* __restrict__ biasKV,
                           float* __restrict__ biasO, float* __restrict__ biasP) {
    int i = blockIdx.x * blockDim.x + threadIdx.x;
    if (i < 2048) {
        biasQ[i] = (i < 1024) ? bqkv_cons[i] : 0.f;
        biasO[i] = (i < 1024) ? bo_cons[i] : bo_conf[i - 1024];
        biasP[i] = (i < 1024) ? bp_cons[i] : bp_conf[i - 1024];
    }
    if (i < 4096) biasKV[i] = (i < 2048) ? bqkv_cons[1024 + i] : bqkv_conf[1024 + (i - 2048)];
}

// ---------------------------------------------------------------------------
// GEMM core (R11/R13-proven): CTA 128x128, BK=64, 8 warps 2(M)x4(N), warp
// tile 64x32, mma.m16n8k16 fp16->fp32, NST=3, ldmatrix A / LDS.128 B.
// ---------------------------------------------------------------------------
#define NST 3
#define SMEM_GEMM (NST * 2048 * 16)   // 98304

template <bool GELU, typename OutT>
__device__ __forceinline__ void gemm_core(
    const uint4* __restrict__ Abase,
    const uint4* __restrict__ Bbase,
    const float* __restrict__ biasb,
    OutT* __restrict__ C, int ldC, int mtb, int ntb,
    uint4* As, uint4* Bs)
{
    const int tid  = threadIdx.x;
    const int wid  = tid >> 5;
    const int lane = tid & 31;
    const int wm   = wid >> 2;
    const int wn   = wid & 3;
    const int g    = lane >> 2;
    const int tig  = lane & 3;

    const uint32_t AsB = (uint32_t)__cvta_generic_to_shared(As);
    const int mm = lane >> 3, ii = lane & 7;
    const int rr = wm * 64 + (mm & 1) * 8 + ii;
    const int LL = rr >> 1, rb = (rr & 1) * 64;
    const int kk = (mm >> 1) * 8;
    auto mkoff = [&](int k) {
        int b = rb + k * 2; int gg = b >> 4;
        int gp = (gg & 4) | ((gg & 3) ^ (LL & 3));
        return (uint32_t)(LL * 128 + gp * 16 + (b & 15));
    };
    const uint32_t aOff0 = mkoff(kk);
    const uint32_t aOff1 = mkoff(kk + 16);

    auto load_stage = [&](int s, int c) {
        const uint4* ga = Abase + (size_t)c * 1024 + tid;
        const uint4* gb = Bbase + (size_t)c * 1024 + tid;
        uint4* sa = As + s * 1024 + tid;
        uint4* sb = Bs + s * 1024 + tid;
#pragma unroll
        for (int j = 0; j < 4; ++j) {
            uint32_t da = (uint32_t)__cvta_generic_to_shared(sa + j * 256);
            asm volatile("cp.async.cg.shared.global [%0], [%1], 16;\n" :: "r"(da), "l"(ga + j * 256));
            uint32_t db = (uint32_t)__cvta_generic_to_shared(sb + j * 256);
            asm volatile("cp.async.cg.shared.global [%0], [%1], 16;\n" :: "r"(db), "l"(gb + j * 256));
        }
        asm volatile("cp.async.commit_group;\n");
    };

    float acc[4][4][4];
#pragma unroll
    for (int i = 0; i < 4; ++i)
#pragma unroll
        for (int j = 0; j < 4; ++j)
#pragma unroll
            for (int k = 0; k < 4; ++k) acc[i][j][k] = 0.f;

#pragma unroll
    for (int s = 0; s < NST - 1; ++s) load_stage(s, s);

    int st = 0, ld = NST - 1;
    for (int c = 0; c < 16; ++c) {
        asm volatile("cp.async.wait_group %0;\n" :: "n"(NST - 2));
        __syncthreads();
        if (c + NST - 1 < 16) {
            load_stage(ld, c + NST - 1);
            if (++ld == NST) ld = 0;
        }
        const uint32_t stA = AsB + st * 16384;
        const uint4* Bbuf = Bs + st * 1024;
#pragma unroll
        for (int ks = 0; ks < 4; ++ks) {
            const int kh  = ks >> 1;
            const int ks2 = ks & 1;
            const uint32_t abase = stA + kh * 8192 + (ks2 ? aOff1 : aOff0);
            const uint4* B4 = Bbuf + kh * 512 + wn * 128 + ks2 * 64 + lane;
            uint32_t a[4][4];
            uint4 bv[2];
#pragma unroll
            for (int mt = 0; mt < 4; ++mt)
                asm volatile("ldmatrix.sync.aligned.m8n8.x4.shared.b16 {%0,%1,%2,%3}, [%4];"
                    : "=r"(a[mt][0]), "=r"(a[mt][1]), "=r"(a[mt][2]), "=r"(a[mt][3])
                    : "r"(abase + mt * 1024));
#pragma unroll
            for (int p = 0; p < 2; ++p)  bv[p] = B4[p * 32];
#pragma unroll
            for (int mt = 0; mt < 4; ++mt) {
#pragma unroll
                for (int p = 0; p < 2; ++p) {
                    asm volatile(
                        "mma.sync.aligned.m16n8k16.row.col.f32.f16.f16.f32 "
                        "{%0,%1,%2,%3}, {%4,%5,%6,%7}, {%8,%9}, {%0,%1,%2,%3};\n"
                        : "+f"(acc[mt][2*p][0]), "+f"(acc[mt][2*p][1]),
                          "+f"(acc[mt][2*p][2]), "+f"(acc[mt][2*p][3])
                        : "r"(a[mt][0]), "r"(a[mt][1]), "r"(a[mt][2]), "r"(a[mt][3]),
                          "r"(bv[p].x), "r"(bv[p].y));
                    asm volatile(
                        "mma.sync.aligned.m16n8k16.row.col.f32.f16.f16.f32 "
                        "{%0,%1,%2,%3}, {%4,%5,%6,%7}, {%8,%9}, {%0,%1,%2,%3};\n"
                        : "+f"(acc[mt][2*p+1][0]), "+f"(acc[mt][2*p+1][1]),
                          "+f"(acc[mt][2*p+1][2]), "+f"(acc[mt][2*p+1][3])
                        : "r"(a[mt][0]), "r"(a[mt][1]), "r"(a[mt][2]), "r"(a[mt][3]),
                          "r"(bv[p].z), "r"(bv[p].w));
                }
            }
        }
        if (++st == NST) st = 0;
    }

    // epilogue
#pragma unroll
    for (int mt = 0; mt < 4; ++mt) {
#pragma unroll
        for (int nt = 0; nt < 4; ++nt) {
            int m = mtb * 128 + wm * 64 + mt * 16 + g;
            int n = ntb * 128 + wn * 32 + nt * 8 + tig * 2;
            float bv0 = biasb[n];
            float bv1 = biasb[n + 1];
            float v0 = acc[mt][nt][0] + bv0;
            float v1 = acc[mt][nt][1] + bv1;
            float v2 = acc[mt][nt][2] + bv0;
            float v3 = acc[mt][nt][3] + bv1;
            if (GELU) {
                v0 = gelu_exact(v0); v1 = gelu_exact(v1);
                v2 = gelu_exact(v2); v3 = gelu_exact(v3);
            }
            if (sizeof(OutT) == 2) {
                __half2* C2 = (__half2*)C;
                C2[((size_t)m       * ldC + n) >> 1] = __floats2half2_rn(v0, v1);
                C2[((size_t)(m + 8) * ldC + n) >> 1] = __floats2half2_rn(v2, v3);
            } else {
                float* Cf = (float*)C;
                *(float2*)&Cf[(size_t)m       * ldC + n] = make_float2(v0, v1);
                *(float2*)&Cf[(size_t)(m + 8) * ldC + n] = make_float2(v2, v3);
            }
        }
    }
}

// Standard GEMM (branch-pair weight select via mtb>>8) — Wo / Wp launches.
template <bool GELU, typename OutT>
__global__ __launch_bounds__(256, 2) void gemm_fp16(
    const uint4* __restrict__ Ap, const uint4* __restrict__ Wp,
    const float* __restrict__ bias, OutT* __restrict__ C, int ldC,
    int wsel_u4, int bias_stride)
{
    extern __shared__ uint4 sm4[];
    const int ntb  = blockIdx.x;
    const int mtb  = blockIdx.y;
    const int bsel = mtb >> 8;
    gemm_core<GELU, OutT>(
        Ap + (size_t)mtb * 16384,
        Wp + (size_t)bsel * wsel_u4 + (size_t)ntb * 16384,
        bias + (size_t)bsel * bias_stride,
        C, ldC, mtb, ntb, sm4, sm4 + NST * 1024);
}

// Fused Q + KV GEMM: flattened grid. ids [0,16384) = KV tiles (32 x 512),
// ids [16384, 20480) = Q tiles (16 x 256).
__global__ __launch_bounds__(256, 2) void gemm_qkv(
    const uint4* __restrict__ Aq,  const uint4* __restrict__ Wq,
    const float* __restrict__ biasQ, __half* __restrict__ Cq,
    const uint4* __restrict__ Akv, const uint4* __restrict__ Wkv,
    const float* __restrict__ biasKV, __half* __restrict__ Ckv)
{
    extern __shared__ uint4 sm4[];
    int id = blockIdx.x;
    if (id < 16384) {
        int ntb = id & 31, mtb = id >> 5;
        gemm_core<false, __half>(
            Akv + (size_t)mtb * 16384, Wkv + (size_t)ntb * 16384,
            biasKV, Ckv, 4096, mtb, ntb, sm4, sm4 + NST * 1024);
    } else {
        id -= 16384;
        int ntb = id & 15, mtb = id >> 4;
        gemm_core<false, __half>(
            Aq + (size_t)mtb * 16384, Wq + (size_t)ntb * 16384,
            biasQ, Cq, 2048, mtb, ntb, sm4, sm4 + NST * 1024);
    }
}

// ---------------------------------------------------------------------------
// Attention (both branches): warp per (branch, b, h). Dense packed writes.
// ---------------------------------------------------------------------------
__global__ __launch_bounds__(256) void attn_kernel(
    const __half* __restrict__ Qout,   // [32768, 2048] cols: Qc | Qf(raw)
    const __half* __restrict__ KV,     // [65536, 4096] cols: Kc | Vc | Kf | Vf
    const float* __restrict__ S, const float* __restrict__ bqkv_conf,
    __half* __restrict__ AOc, __half* __restrict__ AOf)
{
    uint32_t gw = (blockIdx.x * blockDim.x + threadIdx.x) >> 5;
    int lane = threadIdx.x & 31;
    uint32_t branch = gw >> 19;
    uint32_t idx = gw & 0x7FFFFu;
    uint32_t b = idx >> 4, h = idx & 15;

    float2 q = __half22float2(*(const __half2*)(Qout + (size_t)b * 2048 + branch * 1024 + h * 64 + 2 * lane));
    if (branch) {
        float s = 1.f + S[b];
        float2 qb = *(const float2*)(bqkv_conf + h * 64 + 2 * lane);
        q.x = fmaf(s, q.x, qb.x);
        q.y = fmaf(s, q.y, qb.y);
    }
    size_t kvb0 = (size_t)b * 4096 + branch * 2048 + h * 64 + 2 * lane;
    size_t kvb1 = (size_t)(32768 + b) * 4096 + branch * 2048 + h * 64 + 2 * lane;
    float2 k0 = __half22float2(*(const __half2*)(KV + kvb0));
    float2 k1 = __half22float2(*(const __half2*)(KV + kvb1));
    float s0 = q.x * k0.x + q.y * k0.y;
    float s1 = q.x * k1.x + q.y * k1.y;
#pragma unroll
    for (int o = 16; o; o >>= 1) {
        s0 += __shfl_xor_sync(0xffffffffu, s0, o);
        s1 += __shfl_xor_sync(0xffffffffu, s1, o);
    }
    s0 *= 0.125f;
    s1 *= 0.125f;
    float mx = fmaxf(s0, s1);
    float e0 = expf(s0 - mx), e1 = expf(s1 - mx);
    float inv = 1.f / (e0 + e1);
    float a0 = e0 * inv, a1 = e1 * inv;
    float2 v0 = __half22float2(*(const __half2*)(KV + kvb0 + 1024));
    float2 v1 = __half22float2(*(const __half2*)(KV + kvb1 + 1024));
    float ox = a0 * v0.x + a1 * v1.x;
    float oy = a0 * v0.y + a1 * v1.y;

    __half* AO = branch ? AOf : AOc;
    *(__half2*)(AO + packA_idx_h(b, h * 64 + 2 * lane)) = __floats2half2_rn(ox, oy);
}

// ---------------------------------------------------------------------------
// LayerNorm (both branches): warp per row; fp16 in, dense packed fp16 out.
// ---------------------------------------------------------------------------
__global__ __launch_bounds__(256) void ln_kernel(
    const __half* __restrict__ X,
    const float* __restrict__ gamma, const float* __restrict__ beta,
    __half* __restrict__ Y)
{
    uint32_t row = (blockIdx.x * blockDim.x + threadIdx.x) >> 5;
    int lane = threadIdx.x & 31;
    const __half2* x2 = (const __half2*)(X + (size_t)row * 1024);
    float2 v[16];
    float s = 0.f, sq = 0.f;
#pragma unroll
    for (int i = 0; i < 16; ++i) {
        v[i] = __half22float2(x2[lane + 32 * i]);
        s += v[i].x + v[i].y;
        sq += v[i].x * v[i].x + v[i].y * v[i].y;
    }
#pragma unroll
    for (int o = 16; o; o >>= 1) {
        s  += __shfl_xor_sync(0xffffffffu, s, o);
        sq += __shfl_xor_sync(0xffffffffu, sq, o);
    }
    float mean = s * (1.f / 1024.f);
    float var  = sq * (1.f / 1024.f) - mean * mean;
    float rr = rsqrtf(var + 1e-5f);
#pragma unroll
    for (int i = 0; i < 16; ++i) {
        int d = 2 * (lane + 32 * i);
        float2 gm = *(const float2*)(gamma + d);
        float2 bt = *(const float2*)(beta + d);
        float y0 = (v[i].x - mean) * rr * gm.x + bt.x;
        float y1 = (v[i].y - mean) * rr * gm.y + bt.y;
        *(__half2*)(Y + packA_idx_h(row, (uint32_t)d)) = __floats2half2_rn(y0, y1);
    }
}

// ---------------------------------------------------------------------------
// Launch
// ---------------------------------------------------------------------------
extern "C" void kernel_launch(void* const* d_in, const int* in_sizes, int n_in,
                              void* d_out, int out_size)
{
    const float* Z_T       = (const float*)d_in[0];
    const float* Z_V       = (const float*)d_in[1];
    const float* Z_A       = (const float*)d_in[2];
    const float* S         = (const float*)d_in[3];
    const float* Wqkv_cons = (const float*)d_in[4];
    const float* bqkv_cons = (const float*)d_in[5];
    const float* Wo_cons   = (const float*)d_in[6];
    const float* bo_cons   = (const float*)d_in[7];
    const float* Wqkv_conf = (const float*)d_in[8];
    const float* bqkv_conf = (const float*)d_in[9];
    const float* Wo_conf   = (const float*)d_in[10];
    const float* bo_conf   = (const float*)d_in[11];
    const float* Wp_cons   = (const float*)d_in[12];
    const float* bp_cons   = (const float*)d_in[13];
    const float* Wp_conf   = (const float*)d_in[14];
    const float* bp_conf   = (const float*)d_in[15];
    const float* gamma     = (const float*)d_in[16];
    const float* beta      = (const float*)d_in[17];
    float* out = (float*)d_out;

    void* pp = nullptr; cudaGetSymbolAddress(&pp, g_pool);
    void* wp = nullptr; cudaGetSymbolAddress(&wp, g_wr);
    __half* hbase = (__half*)pp;
    __half* wh    = (__half*)wp;
    float*  wrf   = (float*)wp;

    float* biasQ  = wrf + 5ull * DD;       // 2048
    float* biasKV = biasQ + 2048;          // 4096
    float* biasO  = biasKV + 4096;         // 2048
    float* biasP  = biasO + 2048;          // 2048

    auto H  = [&](unsigned long long off) { return hbase + off; };
    auto H4 = [&](unsigned long long off) { return (const uint4*)(hbase + off); };
    auto W4 = [&](unsigned long long dd) { return (const uint4*)(wh + dd * DD); };
    const int WSEL = (int)(DD / 8);

    cudaFuncSetAttribute(gemm_qkv,                 cudaFuncAttributeMaxDynamicSharedMemorySize, SMEM_GEMM);
    cudaFuncSetAttribute(gemm_fp16<false, __half>, cudaFuncAttributeMaxDynamicSharedMemorySize, SMEM_GEMM);
    cudaFuncSetAttribute(gemm_fp16<true,  float>,  cudaFuncAttributeMaxDynamicSharedMemorySize, SMEM_GEMM);

    // --- All packs in 3 launches ---
    PackASrcs pa; pa.src[0] = Z_V; pa.src[1] = Z_A; pa.src[2] = Z_T;
    pack_a_all<<<24576, 256>>>(pa, H(OFF_ZVA), H(OFF_ZT));

    PackWSrcs pw;
    pw.src[0] = Wqkv_cons;            // Wq_c  -> wh + 0*DD
    pw.src[1] = Wqkv_conf;            // Wq_f  -> wh + 1*DD
    pw.src[2] = Wqkv_cons + DD;       // Wk_c  -> wh + 2*DD
    pw.src[3] = Wqkv_cons + 2 * DD;   // Wv_c  -> wh + 3*DD
    pw.src[4] = Wqkv_conf + DD;       // Wk_f  -> wh + 4*DD
    pw.src[5] = Wqkv_conf + 2 * DD;   // Wv_f  -> wh + 5*DD
    pw.src[6] = Wo_cons;              // -> wh + 6*DD
    pw.src[7] = Wo_conf;              // -> wh + 7*DD
    pw.src[8] = Wp_cons;              // -> wh + 8*DD
    pw.src[9] = Wp_conf;              // -> wh + 9*DD
    pack_w_all<<<2560, 256>>>(pw, wh);

    build_bias<<<16, 256>>>(bqkv_cons, bqkv_conf, bo_cons, bo_conf, bp_cons, bp_conf,
                            biasQ, biasKV, biasO, biasP);

    // --- Fused Q + KV GEMM: 16384 KV tiles + 4096 Q tiles ---
    gemm_qkv<<<20480, 256, SMEM_GEMM>>>(
        H4(OFF_ZT),  W4(0), biasQ,  H(OFF_QOUT),
        H4(OFF_ZVA), W4(2), biasKV, H(OFF_KV));

    // --- Attention ---
    attn_kernel<<<131072, 256>>>(H(OFF_QOUT), H(OFF_KV), S, bqkv_conf, H(OFF_AOC), H(OFF_AOF));

    // --- Output projection (both branches) ---
    gemm_fp16<false, __half><<<dim3(8, 512), 256, SMEM_GEMM>>>(
        H4(OFF_AOC), W4(6), biasO, H(OFF_C), 1024, WSEL, 1024);

    // --- LayerNorm (both branches) ---
    ln_kernel<<<8192, 256>>>(H(OFF_C), gamma, beta, H(OFF_LN));

    // --- Final projection + exact GELU into d_out ---
    gemm_fp16<true, float><<<dim3(8, 512), 256, SMEM_GEMM>>>(
        H4(OFF_LN), W4(8), biasP, out, 1024, WSEL, 1024);
}

// round 15
// speedup vs baseline: 1.0085x; 1.0085x over previous
#include <cuda_runtime.h>
#include <cuda_fp16.h>
#include <cstdint>
#include <cstddef>

// ---------------------------------------------------------------------------
// Problem constants
// ---------------------------------------------------------------------------
#define BROWS  32768
#define DMODEL 1024
#define NHEADS 16
#define HDIM   64

// Scratch (__device__ globals = allocation-guard-safe)
#define SLOT_ELEMS 33554432ull                  // B*D elements
__device__ float g_pool[11ull * SLOT_ELEMS];
#define DD 1048576ull
__device__ float g_wr[5ull * DD + 10240];

// fp16 region offsets (halves, from hbase = (half*)g_pool)
#define OFF_ZT   0ull
#define OFF_ZVA  33554432ull     // 32Mi
#define OFF_QOUT 100663296ull    // 96Mi
#define OFF_KV   167772160ull    // 160Mi  (65536 x 4096)
#define OFF_AOC  436207616ull    // 416Mi
#define OFF_AOF  469762048ull    // 448Mi (contiguous after AOC)
#define OFF_C    503316480ull    // 480Mi
#define OFF_LN   570425344ull    // 544Mi

// ---------------------------------------------------------------------------
// Helpers
// ---------------------------------------------------------------------------
__device__ __forceinline__ float gelu_exact(float x) {
    return 0.5f * x * (1.0f + erff(x * 0.70710678118654752440f));
}
__device__ __forceinline__ void stcs_u32(__half2* p, __half2 v) {
    asm volatile("st.global.cs.b32 [%0], %1;" :: "l"(p), "r"(*(uint32_t*)&v) : "memory");
}
__device__ __forceinline__ float2 ldcs_h2(const __half* p) {
    uint32_t u;
    asm volatile("ld.global.cs.b32 %0, [%1];" : "=r"(u) : "l"(p));
    return __half22float2(*(__half2*)&u);
}

// Packed-A layout v2 (R11): chunk (mtile of 128 rows, kb of 32 cols) = 8KB.
// line L = r>>1 holds rows 2L,2L+1 (128B); 16B granules XOR-swizzled by (L&3)
// within each 64B half. ldmatrix-conflict-free AND dense writer rows.
__device__ __forceinline__ size_t packA_idx_h(uint32_t row, uint32_t col) {
    uint32_t mtile = row >> 7, r = row & 127;
    uint32_t kb = col >> 5, c = col & 31;
    uint32_t L = r >> 1;
    uint32_t b = (r & 1) * 64 + c * 2;
    uint32_t g = b >> 4;
    uint32_t gp = (g & 4) | ((g & 3) ^ (L & 3));
    uint32_t byte = L * 128 + gp * 16 + (b & 15);
    return (((size_t)(mtile * 32 + kb)) << 12) + (byte >> 1);
}

// ---------------------------------------------------------------------------
// Pack kernels (smem-staged, coalesced)
// ---------------------------------------------------------------------------
__global__ __launch_bounds__(256) void pack_a(const float* __restrict__ src, __half* __restrict__ dst) {
    __shared__ float sm[128][34];
    uint32_t chunk = blockIdx.x;
    uint32_t mtile = chunk >> 5, kb = chunk & 31;
    const float* base = src + (size_t)mtile * 131072 + kb * 32;
    int t = threadIdx.x;
    int r0 = t >> 3, c4 = (t & 7) * 4;
#pragma unroll
    for (int i = 0; i < 4; ++i) {
        int r = r0 + i * 32;
        float4 v = *(const float4*)(base + (size_t)r * 1024 + c4);
        sm[r][c4] = v.x; sm[r][c4 + 1] = v.y; sm[r][c4 + 2] = v.z; sm[r][c4 + 3] = v.w;
    }
    __syncthreads();
    uint4* out = (uint4*)dst + ((size_t)chunk << 9);
#pragma unroll
    for (int j = 0; j < 2; ++j) {
        int G = t * 2 + j;
        int L = G >> 3, gp = G & 7;
        int g = (gp & 4) | ((gp & 3) ^ (L & 3));
        int b = g * 16;
        int r = 2 * L + (b >= 64 ? 1 : 0);
        int c0 = (b & 63) >> 1;
        __half2 h0 = __floats2half2_rn(sm[r][c0],     sm[r][c0 + 1]);
        __half2 h1 = __floats2half2_rn(sm[r][c0 + 2], sm[r][c0 + 3]);
        __half2 h2 = __floats2half2_rn(sm[r][c0 + 4], sm[r][c0 + 5]);
        __half2 h3 = __floats2half2_rn(sm[r][c0 + 6], sm[r][c0 + 7]);
        uint4 o;
        o.x = *(uint32_t*)&h0; o.y = *(uint32_t*)&h1;
        o.z = *(uint32_t*)&h2; o.w = *(uint32_t*)&h3;
        out[G] = o;
    }
}
// Weight pack (fragment-major; B path uses LDS.128)
__global__ __launch_bounds__(256) void pack_w(const float* __restrict__ src, __half* __restrict__ dst) {
    __shared__ float sm[128][34];
    uint32_t chunk = blockIdx.x;
    uint32_t ntile = chunk >> 5, kb = chunk & 31;
    const float* base = src + (size_t)ntile * 131072 + kb * 32;
    int t = threadIdx.x;
    int r0 = t >> 3, c4 = (t & 7) * 4;
#pragma unroll
    for (int i = 0; i < 4; ++i) {
        int r = r0 + i * 32;
        float4 v = *(const float4*)(base + (size_t)r * 1024 + c4);
        sm[r][c4] = v.x; sm[r][c4 + 1] = v.y; sm[r][c4 + 2] = v.z; sm[r][c4 + 3] = v.w;
    }
    __syncthreads();
    uint4* out = (uint4*)dst + ((size_t)chunk << 9);
#pragma unroll
    for (int i = 0; i < 2; ++i) {
        int w = t + i * 256;
        int lane = w & 31, p = (w >> 5) & 1, ks = (w >> 6) & 1, wn = (w >> 7) & 3;
        int g = lane >> 2, tig = lane & 3;
        int n0 = wn * 32 + p * 16 + g;
        int k0 = ks * 16 + tig * 2;
        __half2 h0 = __floats2half2_rn(sm[n0][k0],         sm[n0][k0 + 1]);
        __half2 h1 = __floats2half2_rn(sm[n0][k0 + 8],     sm[n0][k0 + 9]);
        __half2 h2 = __floats2half2_rn(sm[n0 + 8][k0],     sm[n0 + 8][k0 + 1]);
        __half2 h3 = __floats2half2_rn(sm[n0 + 8][k0 + 8], sm[n0 + 8][k0 + 9]);
        uint4 o;
        o.x = *(uint32_t*)&h0; o.y = *(uint32_t*)&h1;
        o.z = *(uint32_t*)&h2; o.w = *(uint32_t*)&h3;
        out[w] = o;
    }
}

// Concatenated bias vectors
__global__ void build_bias(const float* __restrict__ bqkv_cons, const float* __restrict__ bqkv_conf,
                           const float* __restrict__ bo_cons, const float* __restrict__ bo_conf,
                           const float* __restrict__ bp_cons, const float* __restrict__ bp_conf,
                           float* __restrict__ biasQ, float* __restrict__ biasKV,
                           float* __restrict__ biasO, float* __restrict__ biasP) {
    int i = blockIdx.x * blockDim.x + threadIdx.x;
    if (i < 2048) {
        biasQ[i] = (i < 1024) ? bqkv_cons[i] : 0.f;
        biasO[i] = (i < 1024) ? bo_cons[i] : bo_conf[i - 1024];
        biasP[i] = (i < 1024) ? bp_cons[i] : bp_conf[i - 1024];
    }
    if (i < 4096) biasKV[i] = (i < 2048) ? bqkv_cons[1024 + i] : bqkv_conf[1024 + (i - 2048)];
}

// ---------------------------------------------------------------------------
// GEMM core (R11/R13-proven): CTA 128x128, BK=64, 8 warps 2(M)x4(N), warp
// tile 64x32, mma.m16n8k16 fp16->fp32, NST=3, ldmatrix A / LDS.128 B.
// fp16 outputs use streaming stores (read-once intermediates).
// ---------------------------------------------------------------------------
#define NST 3
#define SMEM_GEMM (NST * 2048 * 16)   // 98304

template <bool GELU, typename OutT>
__device__ __forceinline__ void gemm_core(
    const uint4* __restrict__ Abase,
    const uint4* __restrict__ Bbase,
    const float* __restrict__ biasb,
    OutT* __restrict__ C, int ldC, int mtb, int ntb,
    uint4* As, uint4* Bs)
{
    const int tid  = threadIdx.x;
    const int wid  = tid >> 5;
    const int lane = tid & 31;
    const int wm   = wid >> 2;
    const int wn   = wid & 3;
    const int g    = lane >> 2;
    const int tig  = lane & 3;

    const uint32_t AsB = (uint32_t)__cvta_generic_to_shared(As);
    const int mm = lane >> 3, ii = lane & 7;
    const int rr = wm * 64 + (mm & 1) * 8 + ii;
    const int LL = rr >> 1, rb = (rr & 1) * 64;
    const int kk = (mm >> 1) * 8;
    auto mkoff = [&](int k) {
        int b = rb + k * 2; int gg = b >> 4;
        int gp = (gg & 4) | ((gg & 3) ^ (LL & 3));
        return (uint32_t)(LL * 128 + gp * 16 + (b & 15));
    };
    const uint32_t aOff0 = mkoff(kk);
    const uint32_t aOff1 = mkoff(kk + 16);

    auto load_stage = [&](int s, int c) {
        const uint4* ga = Abase + (size_t)c * 1024 + tid;
        const uint4* gb = Bbase + (size_t)c * 1024 + tid;
        uint4* sa = As + s * 1024 + tid;
        uint4* sb = Bs + s * 1024 + tid;
#pragma unroll
        for (int j = 0; j < 4; ++j) {
            uint32_t da = (uint32_t)__cvta_generic_to_shared(sa + j * 256);
            asm volatile("cp.async.cg.shared.global [%0], [%1], 16;\n" :: "r"(da), "l"(ga + j * 256));
            uint32_t db = (uint32_t)__cvta_generic_to_shared(sb + j * 256);
            asm volatile("cp.async.cg.shared.global [%0], [%1], 16;\n" :: "r"(db), "l"(gb + j * 256));
        }
        asm volatile("cp.async.commit_group;\n");
    };

    float acc[4][4][4];
#pragma unroll
    for (int i = 0; i < 4; ++i)
#pragma unroll
        for (int j = 0; j < 4; ++j)
#pragma unroll
            for (int k = 0; k < 4; ++k) acc[i][j][k] = 0.f;

#pragma unroll
    for (int s = 0; s < NST - 1; ++s) load_stage(s, s);

    int st = 0, ld = NST - 1;
    for (int c = 0; c < 16; ++c) {
        asm volatile("cp.async.wait_group %0;\n" :: "n"(NST - 2));
        __syncthreads();
        if (c + NST - 1 < 16) {
            load_stage(ld, c + NST - 1);
            if (++ld == NST) ld = 0;
        }
        const uint32_t stA = AsB + st * 16384;
        const uint4* Bbuf = Bs + st * 1024;
#pragma unroll
        for (int ks = 0; ks < 4; ++ks) {
            const int kh  = ks >> 1;
            const int ks2 = ks & 1;
            const uint32_t abase = stA + kh * 8192 + (ks2 ? aOff1 : aOff0);
            const uint4* B4 = Bbuf + kh * 512 + wn * 128 + ks2 * 64 + lane;
            uint32_t a[4][4];
            uint4 bv[2];
#pragma unroll
            for (int mt = 0; mt < 4; ++mt)
                asm volatile("ldmatrix.sync.aligned.m8n8.x4.shared.b16 {%0,%1,%2,%3}, [%4];"
                    : "=r"(a[mt][0]), "=r"(a[mt][1]), "=r"(a[mt][2]), "=r"(a[mt][3])
                    : "r"(abase + mt * 1024));
#pragma unroll
            for (int p = 0; p < 2; ++p)  bv[p] = B4[p * 32];
#pragma unroll
            for (int mt = 0; mt < 4; ++mt) {
#pragma unroll
                for (int p = 0; p < 2; ++p) {
                    asm volatile(
                        "mma.sync.aligned.m16n8k16.row.col.f32.f16.f16.f32 "
                        "{%0,%1,%2,%3}, {%4,%5,%6,%7}, {%8,%9}, {%0,%1,%2,%3};\n"
                        : "+f"(acc[mt][2*p][0]), "+f"(acc[mt][2*p][1]),
                          "+f"(acc[mt][2*p][2]), "+f"(acc[mt][2*p][3])
                        : "r"(a[mt][0]), "r"(a[mt][1]), "r"(a[mt][2]), "r"(a[mt][3]),
                          "r"(bv[p].x), "r"(bv[p].y));
                    asm volatile(
                        "mma.sync.aligned.m16n8k16.row.col.f32.f16.f16.f32 "
                        "{%0,%1,%2,%3}, {%4,%5,%6,%7}, {%8,%9}, {%0,%1,%2,%3};\n"
                        : "+f"(acc[mt][2*p+1][0]), "+f"(acc[mt][2*p+1][1]),
                          "+f"(acc[mt][2*p+1][2]), "+f"(acc[mt][2*p+1][3])
                        : "r"(a[mt][0]), "r"(a[mt][1]), "r"(a[mt][2]), "r"(a[mt][3]),
                          "r"(bv[p].z), "r"(bv[p].w));
                }
            }
        }
        if (++st == NST) st = 0;
    }

    // epilogue
#pragma unroll
    for (int mt = 0; mt < 4; ++mt) {
#pragma unroll
        for (int nt = 0; nt < 4; ++nt) {
            int m = mtb * 128 + wm * 64 + mt * 16 + g;
            int n = ntb * 128 + wn * 32 + nt * 8 + tig * 2;
            float bv0 = biasb[n];
            float bv1 = biasb[n + 1];
            float v0 = acc[mt][nt][0] + bv0;
            float v1 = acc[mt][nt][1] + bv1;
            float v2 = acc[mt][nt][2] + bv0;
            float v3 = acc[mt][nt][3] + bv1;
            if (GELU) {
                v0 = gelu_exact(v0); v1 = gelu_exact(v1);
                v2 = gelu_exact(v2); v3 = gelu_exact(v3);
            }
            if (sizeof(OutT) == 2) {
                __half2* C2 = (__half2*)C;
                stcs_u32(C2 + (((size_t)m       * ldC + n) >> 1), __floats2half2_rn(v0, v1));
                stcs_u32(C2 + (((size_t)(m + 8) * ldC + n) >> 1), __floats2half2_rn(v2, v3));
            } else {
                float* Cf = (float*)C;
                *(float2*)&Cf[(size_t)m       * ldC + n] = make_float2(v0, v1);
                *(float2*)&Cf[(size_t)(m + 8) * ldC + n] = make_float2(v2, v3);
            }
        }
    }
}

// Standard GEMM (branch-pair weight select via mtb>>8) — Wo / Wp launches.
template <bool GELU, typename OutT>
__global__ __launch_bounds__(256, 2) void gemm_fp16(
    const uint4* __restrict__ Ap, const uint4* __restrict__ Wp,
    const float* __restrict__ bias, OutT* __restrict__ C, int ldC,
    int wsel_u4, int bias_stride)
{
    extern __shared__ uint4 sm4[];
    const int ntb  = blockIdx.x;
    const int mtb  = blockIdx.y;
    const int bsel = mtb >> 8;
    gemm_core<GELU, OutT>(
        Ap + (size_t)mtb * 16384,
        Wp + (size_t)bsel * wsel_u4 + (size_t)ntb * 16384,
        bias + (size_t)bsel * bias_stride,
        C, ldC, mtb, ntb, sm4, sm4 + NST * 1024);
}

// Fused Q + KV GEMM: flattened grid. ids [0,16384) = KV tiles (32 x 512),
// ids [16384, 20480) = Q tiles (16 x 256).
__global__ __launch_bounds__(256, 2) void gemm_qkv(
    const uint4* __restrict__ Aq,  const uint4* __restrict__ Wq,
    const float* __restrict__ biasQ, __half* __restrict__ Cq,
    const uint4* __restrict__ Akv, const uint4* __restrict__ Wkv,
    const float* __restrict__ biasKV, __half* __restrict__ Ckv)
{
    extern __shared__ uint4 sm4[];
    int id = blockIdx.x;
    if (id < 16384) {
        int ntb = id & 31, mtb = id >> 5;
        gemm_core<false, __half>(
            Akv + (size_t)mtb * 16384, Wkv + (size_t)ntb * 16384,
            biasKV, Ckv, 4096, mtb, ntb, sm4, sm4 + NST * 1024);
    } else {
        id -= 16384;
        int ntb = id & 15, mtb = id >> 4;
        gemm_core<false, __half>(
            Aq + (size_t)mtb * 16384, Wq + (size_t)ntb * 16384,
            biasQ, Cq, 2048, mtb, ntb, sm4, sm4 + NST * 1024);
    }
}

// ---------------------------------------------------------------------------
// Attention (both branches): warp per (branch, b, h). Streaming (read-once)
// loads of Qout/KV; dense packed writes.
// ---------------------------------------------------------------------------
__global__ __launch_bounds__(256) void attn_kernel(
    const __half* __restrict__ Qout,   // [32768, 2048] cols: Qc | Qf(raw)
    const __half* __restrict__ KV,     // [65536, 4096] cols: Kc | Vc | Kf | Vf
    const float* __restrict__ S, const float* __restrict__ bqkv_conf,
    __half* __restrict__ AOc, __half* __restrict__ AOf)
{
    uint32_t gw = (blockIdx.x * blockDim.x + threadIdx.x) >> 5;
    int lane = threadIdx.x & 31;
    uint32_t branch = gw >> 19;
    uint32_t idx = gw & 0x7FFFFu;
    uint32_t b = idx >> 4, h = idx & 15;

    float2 q = ldcs_h2(Qout + (size_t)b * 2048 + branch * 1024 + h * 64 + 2 * lane);
    if (branch) {
        float s = 1.f + S[b];
        float2 qb = *(const float2*)(bqkv_conf + h * 64 + 2 * lane);
        q.x = fmaf(s, q.x, qb.x);
        q.y = fmaf(s, q.y, qb.y);
    }
    size_t kvb0 = (size_t)b * 4096 + branch * 2048 + h * 64 + 2 * lane;
    size_t kvb1 = (size_t)(32768 + b) * 4096 + branch * 2048 + h * 64 + 2 * lane;
    float2 k0 = ldcs_h2(KV + kvb0);
    float2 k1 = ldcs_h2(KV + kvb1);
    float s0 = q.x * k0.x + q.y * k0.y;
    float s1 = q.x * k1.x + q.y * k1.y;
#pragma unroll
    for (int o = 16; o; o >>= 1) {
        s0 += __shfl_xor_sync(0xffffffffu, s0, o);
        s1 += __shfl_xor_sync(0xffffffffu, s1, o);
    }
    s0 *= 0.125f;
    s1 *= 0.125f;
    float mx = fmaxf(s0, s1);
    float e0 = expf(s0 - mx), e1 = expf(s1 - mx);
    float inv = 1.f / (e0 + e1);
    float a0 = e0 * inv, a1 = e1 * inv;
    float2 v0 = ldcs_h2(KV + kvb0 + 1024);
    float2 v1 = ldcs_h2(KV + kvb1 + 1024);
    float ox = a0 * v0.x + a1 * v1.x;
    float oy = a0 * v0.y + a1 * v1.y;

    __half* AO = branch ? AOf : AOc;
    *(__half2*)(AO + packA_idx_h(b, h * 64 + 2 * lane)) = __floats2half2_rn(ox, oy);
}

// ---------------------------------------------------------------------------
// LayerNorm (both branches): warp per row; streaming fp16 in, packed fp16 out.
// ---------------------------------------------------------------------------
__global__ __launch_bounds__(256) void ln_kernel(
    const __half* __restrict__ X,
    const float* __restrict__ gamma, const float* __restrict__ beta,
    __half* __restrict__ Y)
{
    uint32_t row = (blockIdx.x * blockDim.x + threadIdx.x) >> 5;
    int lane = threadIdx.x & 31;
    const __half2* x2 = (const __half2*)(X + (size_t)row * 1024);
    float2 v[16];
    float s = 0.f, sq = 0.f;
#pragma unroll
    for (int i = 0; i < 16; ++i) {
        v[i] = __half22float2(__ldcs(x2 + lane + 32 * i));
        s += v[i].x + v[i].y;
        sq += v[i].x * v[i].x + v[i].y * v[i].y;
    }
#pragma unroll
    for (int o = 16; o; o >>= 1) {
        s  += __shfl_xor_sync(0xffffffffu, s, o);
        sq += __shfl_xor_sync(0xffffffffu, sq, o);
    }
    float mean = s * (1.f / 1024.f);
    float var  = sq * (1.f / 1024.f) - mean * mean;
    float rr = rsqrtf(var + 1e-5f);
#pragma unroll
    for (int i = 0; i < 16; ++i) {
        int d = 2 * (lane + 32 * i);
        float2 gm = *(const float2*)(gamma + d);
        float2 bt = *(const float2*)(beta + d);
        float y0 = (v[i].x - mean) * rr * gm.x + bt.x;
        float y1 = (v[i].y - mean) * rr * gm.y + bt.y;
        *(__half2*)(Y + packA_idx_h(row, (uint32_t)d)) = __floats2half2_rn(y0, y1);
    }
}

// ---------------------------------------------------------------------------
// Launch (R13 structure — measured best)
// ---------------------------------------------------------------------------
extern "C" void kernel_launch(void* const* d_in, const int* in_sizes, int n_in,
                              void* d_out, int out_size)
{
    const float* Z_T       = (const float*)d_in[0];
    const float* Z_V       = (const float*)d_in[1];
    const float* Z_A       = (const float*)d_in[2];
    const float* S         = (const float*)d_in[3];
    const float* Wqkv_cons = (const float*)d_in[4];
    const float* bqkv_cons = (const float*)d_in[5];
    const float* Wo_cons   = (const float*)d_in[6];
    const float* bo_cons   = (const float*)d_in[7];
    const float* Wqkv_conf = (const float*)d_in[8];
    const float* bqkv_conf = (const float*)d_in[9];
    const float* Wo_conf   = (const float*)d_in[10];
    const float* bo_conf   = (const float*)d_in[11];
    const float* Wp_cons   = (const float*)d_in[12];
    const float* bp_cons   = (const float*)d_in[13];
    const float* Wp_conf   = (const float*)d_in[14];
    const float* bp_conf   = (const float*)d_in[15];
    const float* gamma     = (const float*)d_in[16];
    const float* beta      = (const float*)d_in[17];
    float* out = (float*)d_out;

    void* pp = nullptr; cudaGetSymbolAddress(&pp, g_pool);
    void* wp = nullptr; cudaGetSymbolAddress(&wp, g_wr);
    __half* hbase = (__half*)pp;
    __half* wh    = (__half*)wp;
    float*  wrf   = (float*)wp;

    float* biasQ  = wrf + 5ull * DD;       // 2048
    float* biasKV = biasQ + 2048;          // 4096
    float* biasO  = biasKV + 4096;         // 2048
    float* biasP  = biasO + 2048;          // 2048

    auto H  = [&](unsigned long long off) { return hbase + off; };
    auto H4 = [&](unsigned long long off) { return (const uint4*)(hbase + off); };
    auto W4 = [&](unsigned long long dd) { return (const uint4*)(wh + dd * DD); };
    const int WSEL = (int)(DD / 8);

    cudaFuncSetAttribute(gemm_qkv,                 cudaFuncAttributeMaxDynamicSharedMemorySize, SMEM_GEMM);
    cudaFuncSetAttribute(gemm_fp16<false, __half>, cudaFuncAttributeMaxDynamicSharedMemorySize, SMEM_GEMM);
    cudaFuncSetAttribute(gemm_fp16<true,  float>,  cudaFuncAttributeMaxDynamicSharedMemorySize, SMEM_GEMM);

    // Packs (all QKV dependencies)
    pack_a<<<8192, 256>>>(Z_V, H(OFF_ZVA));
    pack_a<<<8192, 256>>>(Z_A, H(OFF_ZVA) + SLOT_ELEMS);
    pack_a<<<8192, 256>>>(Z_T, H(OFF_ZT));
    pack_w<<<512, 256>>>(Wqkv_cons + DD, wh + 2ull * DD);         // Wk_c, Wv_c
    pack_w<<<512, 256>>>(Wqkv_conf + DD, wh + 4ull * DD);         // Wk_f, Wv_f
    pack_w<<<256, 256>>>(Wqkv_cons, wh + 0ull * DD);              // Wq_c
    pack_w<<<256, 256>>>(Wqkv_conf, wh + 1ull * DD);              // Wq_f
    build_bias<<<16, 256>>>(bqkv_cons, bqkv_conf, bo_cons, bo_conf, bp_cons, bp_conf,
                            biasQ, biasKV, biasO, biasP);

    // Fused Q + KV GEMM: 16384 KV tiles + 4096 Q tiles in one launch
    gemm_qkv<<<20480, 256, SMEM_GEMM>>>(
        H4(OFF_ZT),  W4(0), biasQ,  H(OFF_QOUT),
        H4(OFF_ZVA), W4(2), biasKV, H(OFF_KV));

    // Attention
    attn_kernel<<<131072, 256>>>(H(OFF_QOUT), H(OFF_KV), S, bqkv_conf, H(OFF_AOC), H(OFF_AOF));

    // Output projection (both branches): [65536, 1024]
    pack_w<<<256, 256>>>(Wo_cons, wh + 6ull * DD);
    pack_w<<<256, 256>>>(Wo_conf, wh + 7ull * DD);
    gemm_fp16<false, __half><<<dim3(8, 512), 256, SMEM_GEMM>>>(
        H4(OFF_AOC), W4(6), biasO, H(OFF_C), 1024, WSEL, 1024);

    // LayerNorm (both branches)
    ln_kernel<<<8192, 256>>>(H(OFF_C), gamma, beta, H(OFF_LN));

    // Final projection + GELU: [65536, 1024] into d_out
    pack_w<<<256, 256>>>(Wp_cons, wh + 8ull * DD);
    pack_w<<<256, 256>>>(Wp_conf, wh + 9ull * DD);
    gemm_fp16<true, float><<<dim3(8, 512), 256, SMEM_GEMM>>>(
        H4(OFF_LN), W4(8), biasP, out, 1024, WSEL, 1024);
}

// round 16
// speedup vs baseline: 1.0103x; 1.0018x over previous
#include <cuda_runtime.h>
#include <cuda_fp16.h>
#include <cstdint>
#include <cstddef>

// ---------------------------------------------------------------------------
// Problem constants
// ---------------------------------------------------------------------------
#define BROWS  32768
#define DMODEL 1024
#define NHEADS 16
#define HDIM   64

// Scratch (__device__ globals = allocation-guard-safe)
#define SLOT_ELEMS 33554432ull                  // B*D elements
__device__ float g_pool[11ull * SLOT_ELEMS];
#define DD 1048576ull
__device__ float g_wr[5ull * DD + 10240];

// fp16 region offsets (halves, from hbase = (half*)g_pool)
#define OFF_ZT   0ull
#define OFF_ZVA  33554432ull     // 32Mi
#define OFF_QOUT 100663296ull    // 96Mi
#define OFF_KV   167772160ull    // 160Mi  (65536 x 4096)
#define OFF_AOC  436207616ull    // 416Mi
#define OFF_AOF  469762048ull    // 448Mi (contiguous after AOC)
#define OFF_C    503316480ull    // 480Mi
#define OFF_LN   570425344ull    // 544Mi

// ---------------------------------------------------------------------------
// Helpers
// ---------------------------------------------------------------------------
__device__ __forceinline__ float gelu_exact(float x) {
    return 0.5f * x * (1.0f + erff(x * 0.70710678118654752440f));
}
__device__ __forceinline__ void stcs_u32(__half2* p, __half2 v) {
    asm volatile("st.global.cs.b32 [%0], %1;" :: "l"(p), "r"(*(uint32_t*)&v) : "memory");
}
__device__ __forceinline__ float2 ldcs_h2(const __half* p) {
    uint32_t u;
    asm volatile("ld.global.cs.b32 %0, [%1];" : "=r"(u) : "l"(p));
    return __half22float2(*(__half2*)&u);
}

// Packed-A layout v2 (R11): chunk (mtile of 128 rows, kb of 32 cols) = 8KB.
// line L = r>>1 holds rows 2L,2L+1 (128B); 16B granules XOR-swizzled by (L&3)
// within each 64B half. ldmatrix-conflict-free AND dense writer rows.
__device__ __forceinline__ size_t packA_idx_h(uint32_t row, uint32_t col) {
    uint32_t mtile = row >> 7, r = row & 127;
    uint32_t kb = col >> 5, c = col & 31;
    uint32_t L = r >> 1;
    uint32_t b = (r & 1) * 64 + c * 2;
    uint32_t g = b >> 4;
    uint32_t gp = (g & 4) | ((g & 3) ^ (L & 3));
    uint32_t byte = L * 128 + gp * 16 + (b & 15);
    return (((size_t)(mtile * 32 + kb)) << 12) + (byte >> 1);
}

// ---------------------------------------------------------------------------
// Pack kernels (smem-staged, coalesced)
// ---------------------------------------------------------------------------
__global__ __launch_bounds__(256) void pack_a(const float* __restrict__ src, __half* __restrict__ dst) {
    __shared__ float sm[128][34];
    uint32_t chunk = blockIdx.x;
    uint32_t mtile = chunk >> 5, kb = chunk & 31;
    const float* base = src + (size_t)mtile * 131072 + kb * 32;
    int t = threadIdx.x;
    int r0 = t >> 3, c4 = (t & 7) * 4;
#pragma unroll
    for (int i = 0; i < 4; ++i) {
        int r = r0 + i * 32;
        float4 v = *(const float4*)(base + (size_t)r * 1024 + c4);
        sm[r][c4] = v.x; sm[r][c4 + 1] = v.y; sm[r][c4 + 2] = v.z; sm[r][c4 + 3] = v.w;
    }
    __syncthreads();
    uint4* out = (uint4*)dst + ((size_t)chunk << 9);
#pragma unroll
    for (int j = 0; j < 2; ++j) {
        int G = t * 2 + j;
        int L = G >> 3, gp = G & 7;
        int g = (gp & 4) | ((gp & 3) ^ (L & 3));
        int b = g * 16;
        int r = 2 * L + (b >= 64 ? 1 : 0);
        int c0 = (b & 63) >> 1;
        __half2 h0 = __floats2half2_rn(sm[r][c0],     sm[r][c0 + 1]);
        __half2 h1 = __floats2half2_rn(sm[r][c0 + 2], sm[r][c0 + 3]);
        __half2 h2 = __floats2half2_rn(sm[r][c0 + 4], sm[r][c0 + 5]);
        __half2 h3 = __floats2half2_rn(sm[r][c0 + 6], sm[r][c0 + 7]);
        uint4 o;
        o.x = *(uint32_t*)&h0; o.y = *(uint32_t*)&h1;
        o.z = *(uint32_t*)&h2; o.w = *(uint32_t*)&h3;
        out[G] = o;
    }
}
// Weight pack (fragment-major; B path uses LDS.128)
__global__ __launch_bounds__(256) void pack_w(const float* __restrict__ src, __half* __restrict__ dst) {
    __shared__ float sm[128][34];
    uint32_t chunk = blockIdx.x;
    uint32_t ntile = chunk >> 5, kb = chunk & 31;
    const float* base = src + (size_t)ntile * 131072 + kb * 32;
    int t = threadIdx.x;
    int r0 = t >> 3, c4 = (t & 7) * 4;
#pragma unroll
    for (int i = 0; i < 4; ++i) {
        int r = r0 + i * 32;
        float4 v = *(const float4*)(base + (size_t)r * 1024 + c4);
        sm[r][c4] = v.x; sm[r][c4 + 1] = v.y; sm[r][c4 + 2] = v.z; sm[r][c4 + 3] = v.w;
    }
    __syncthreads();
    uint4* out = (uint4*)dst + ((size_t)chunk << 9);
#pragma unroll
    for (int i = 0; i < 2; ++i) {
        int w = t + i * 256;
        int lane = w & 31, p = (w >> 5) & 1, ks = (w >> 6) & 1, wn = (w >> 7) & 3;
        int g = lane >> 2, tig = lane & 3;
        int n0 = wn * 32 + p * 16 + g;
        int k0 = ks * 16 + tig * 2;
        __half2 h0 = __floats2half2_rn(sm[n0][k0],         sm[n0][k0 + 1]);
        __half2 h1 = __floats2half2_rn(sm[n0][k0 + 8],     sm[n0][k0 + 9]);
        __half2 h2 = __floats2half2_rn(sm[n0 + 8][k0],     sm[n0 + 8][k0 + 1]);
        __half2 h3 = __floats2half2_rn(sm[n0 + 8][k0 + 8], sm[n0 + 8][k0 + 9]);
        uint4 o;
        o.x = *(uint32_t*)&h0; o.y = *(uint32_t*)&h1;
        o.z = *(uint32_t*)&h2; o.w = *(uint32_t*)&h3;
        out[w] = o;
    }
}

// Concatenated bias vectors
__global__ void build_bias(const float* __restrict__ bqkv_cons, const float* __restrict__ bqkv_conf,
                           const float* __restrict__ bo_cons, const float* __restrict__ bo_conf,
                           const float* __restrict__ bp_cons, const float* __restrict__ bp_conf,
                           float* __restrict__ biasQ, float* __restrict__ biasKV,
                           float* __restrict__ biasO, float* __restrict__ biasP) {
    int i = blockIdx.x * blockDim.x + threadIdx.x;
    if (i < 2048) {
        biasQ[i] = (i < 1024) ? bqkv_cons[i] : 0.f;
        biasO[i] = (i < 1024) ? bo_cons[i] : bo_conf[i - 1024];
        biasP[i] = (i < 1024) ? bp_cons[i] : bp_conf[i - 1024];
    }
    if (i < 4096) biasKV[i] = (i < 2048) ? bqkv_cons[1024 + i] : bqkv_conf[1024 + (i - 2048)];
}

// ---------------------------------------------------------------------------
// GEMM core (R11/R13-proven): CTA 128x128, BK=64, 8 warps 2(M)x4(N), warp
// tile 64x32, mma.m16n8k16 fp16->fp32, NST=3, ldmatrix A / LDS.128 B.
// fp16 outputs use streaming stores (read-once intermediates).
// ---------------------------------------------------------------------------
#define NST 3
#define SMEM_GEMM (NST * 2048 * 16)   // 98304

template <bool GELU, typename OutT>
__device__ __forceinline__ void gemm_core(
    const uint4* __restrict__ Abase,
    const uint4* __restrict__ Bbase,
    const float* __restrict__ biasb,
    OutT* __restrict__ C, int ldC, int mtb, int ntb,
    uint4* As, uint4* Bs)
{
    const int tid  = threadIdx.x;
    const int wid  = tid >> 5;
    const int lane = tid & 31;
    const int wm   = wid >> 2;
    const int wn   = wid & 3;
    const int g    = lane >> 2;
    const int tig  = lane & 3;

    const uint32_t AsB = (uint32_t)__cvta_generic_to_shared(As);
    const int mm = lane >> 3, ii = lane & 7;
    const int rr = wm * 64 + (mm & 1) * 8 + ii;
    const int LL = rr >> 1, rb = (rr & 1) * 64;
    const int kk = (mm >> 1) * 8;
    auto mkoff = [&](int k) {
        int b = rb + k * 2; int gg = b >> 4;
        int gp = (gg & 4) | ((gg & 3) ^ (LL & 3));
        return (uint32_t)(LL * 128 + gp * 16 + (b & 15));
    };
    const uint32_t aOff0 = mkoff(kk);
    const uint32_t aOff1 = mkoff(kk + 16);

    auto load_stage = [&](int s, int c) {
        const uint4* ga = Abase + (size_t)c * 1024 + tid;
        const uint4* gb = Bbase + (size_t)c * 1024 + tid;
        uint4* sa = As + s * 1024 + tid;
        uint4* sb = Bs + s * 1024 + tid;
#pragma unroll
        for (int j = 0; j < 4; ++j) {
            uint32_t da = (uint32_t)__cvta_generic_to_shared(sa + j * 256);
            asm volatile("cp.async.cg.shared.global [%0], [%1], 16;\n" :: "r"(da), "l"(ga + j * 256));
            uint32_t db = (uint32_t)__cvta_generic_to_shared(sb + j * 256);
            asm volatile("cp.async.cg.shared.global [%0], [%1], 16;\n" :: "r"(db), "l"(gb + j * 256));
        }
        asm volatile("cp.async.commit_group;\n");
    };

    float acc[4][4][4];
#pragma unroll
    for (int i = 0; i < 4; ++i)
#pragma unroll
        for (int j = 0; j < 4; ++j)
#pragma unroll
            for (int k = 0; k < 4; ++k) acc[i][j][k] = 0.f;

#pragma unroll
    for (int s = 0; s < NST - 1; ++s) load_stage(s, s);

    int st = 0, ld = NST - 1;
    for (int c = 0; c < 16; ++c) {
        asm volatile("cp.async.wait_group %0;\n" :: "n"(NST - 2));
        __syncthreads();
        if (c + NST - 1 < 16) {
            load_stage(ld, c + NST - 1);
            if (++ld == NST) ld = 0;
        }
        const uint32_t stA = AsB + st * 16384;
        const uint4* Bbuf = Bs + st * 1024;
#pragma unroll
        for (int ks = 0; ks < 4; ++ks) {
            const int kh  = ks >> 1;
            const int ks2 = ks & 1;
            const uint32_t abase = stA + kh * 8192 + (ks2 ? aOff1 : aOff0);
            const uint4* B4 = Bbuf + kh * 512 + wn * 128 + ks2 * 64 + lane;
            uint32_t a[4][4];
            uint4 bv[2];
#pragma unroll
            for (int mt = 0; mt < 4; ++mt)
                asm volatile("ldmatrix.sync.aligned.m8n8.x4.shared.b16 {%0,%1,%2,%3}, [%4];"
                    : "=r"(a[mt][0]), "=r"(a[mt][1]), "=r"(a[mt][2]), "=r"(a[mt][3])
                    : "r"(abase + mt * 1024));
#pragma unroll
            for (int p = 0; p < 2; ++p)  bv[p] = B4[p * 32];
#pragma unroll
            for (int mt = 0; mt < 4; ++mt) {
#pragma unroll
                for (int p = 0; p < 2; ++p) {
                    asm volatile(
                        "mma.sync.aligned.m16n8k16.row.col.f32.f16.f16.f32 "
                        "{%0,%1,%2,%3}, {%4,%5,%6,%7}, {%8,%9}, {%0,%1,%2,%3};\n"
                        : "+f"(acc[mt][2*p][0]), "+f"(acc[mt][2*p][1]),
                          "+f"(acc[mt][2*p][2]), "+f"(acc[mt][2*p][3])
                        : "r"(a[mt][0]), "r"(a[mt][1]), "r"(a[mt][2]), "r"(a[mt][3]),
                          "r"(bv[p].x), "r"(bv[p].y));
                    asm volatile(
                        "mma.sync.aligned.m16n8k16.row.col.f32.f16.f16.f32 "
                        "{%0,%1,%2,%3}, {%4,%5,%6,%7}, {%8,%9}, {%0,%1,%2,%3};\n"
                        : "+f"(acc[mt][2*p+1][0]), "+f"(acc[mt][2*p+1][1]),
                          "+f"(acc[mt][2*p+1][2]), "+f"(acc[mt][2*p+1][3])
                        : "r"(a[mt][0]), "r"(a[mt][1]), "r"(a[mt][2]), "r"(a[mt][3]),
                          "r"(bv[p].z), "r"(bv[p].w));
                }
            }
        }
        if (++st == NST) st = 0;
    }

    // epilogue
#pragma unroll
    for (int mt = 0; mt < 4; ++mt) {
#pragma unroll
        for (int nt = 0; nt < 4; ++nt) {
            int m = mtb * 128 + wm * 64 + mt * 16 + g;
            int n = ntb * 128 + wn * 32 + nt * 8 + tig * 2;
            float bv0 = biasb[n];
            float bv1 = biasb[n + 1];
            float v0 = acc[mt][nt][0] + bv0;
            float v1 = acc[mt][nt][1] + bv1;
            float v2 = acc[mt][nt][2] + bv0;
            float v3 = acc[mt][nt][3] + bv1;
            if (GELU) {
                v0 = gelu_exact(v0); v1 = gelu_exact(v1);
                v2 = gelu_exact(v2); v3 = gelu_exact(v3);
            }
            if (sizeof(OutT) == 2) {
                __half2* C2 = (__half2*)C;
                stcs_u32(C2 + (((size_t)m       * ldC + n) >> 1), __floats2half2_rn(v0, v1));
                stcs_u32(C2 + (((size_t)(m + 8) * ldC + n) >> 1), __floats2half2_rn(v2, v3));
            } else {
                float* Cf = (float*)C;
                *(float2*)&Cf[(size_t)m       * ldC + n] = make_float2(v0, v1);
                *(float2*)&Cf[(size_t)(m + 8) * ldC + n] = make_float2(v2, v3);
            }
        }
    }
}

// Standard GEMM (branch-pair weight select via mtb>>8) — Wo / Wp launches.
template <bool GELU, typename OutT>
__global__ __launch_bounds__(256, 2) void gemm_fp16(
    const uint4* __restrict__ Ap, const uint4* __restrict__ Wp,
    const float* __restrict__ bias, OutT* __restrict__ C, int ldC,
    int wsel_u4, int bias_stride)
{
    extern __shared__ uint4 sm4[];
    const int ntb  = blockIdx.x;
    const int mtb  = blockIdx.y;
    const int bsel = mtb >> 8;
    gemm_core<GELU, OutT>(
        Ap + (size_t)mtb * 16384,
        Wp + (size_t)bsel * wsel_u4 + (size_t)ntb * 16384,
        bias + (size_t)bsel * bias_stride,
        C, ldC, mtb, ntb, sm4, sm4 + NST * 1024);
}

// Fused Q + KV GEMM: flattened grid. ids [0,16384) = KV tiles (32 x 512),
// ids [16384, 20480) = Q tiles (16 x 256).
__global__ __launch_bounds__(256, 2) void gemm_qkv(
    const uint4* __restrict__ Aq,  const uint4* __restrict__ Wq,
    const float* __restrict__ biasQ, __half* __restrict__ Cq,
    const uint4* __restrict__ Akv, const uint4* __restrict__ Wkv,
    const float* __restrict__ biasKV, __half* __restrict__ Ckv)
{
    extern __shared__ uint4 sm4[];
    int id = blockIdx.x;
    if (id < 16384) {
        int ntb = id & 31, mtb = id >> 5;
        gemm_core<false, __half>(
            Akv + (size_t)mtb * 16384, Wkv + (size_t)ntb * 16384,
            biasKV, Ckv, 4096, mtb, ntb, sm4, sm4 + NST * 1024);
    } else {
        id -= 16384;
        int ntb = id & 15, mtb = id >> 4;
        gemm_core<false, __half>(
            Aq + (size_t)mtb * 16384, Wq + (size_t)ntb * 16384,
            biasQ, Cq, 2048, mtb, ntb, sm4, sm4 + NST * 1024);
    }
}

// ---------------------------------------------------------------------------
// Attention (both branches): warp per (branch, b, h). Streaming (read-once)
// loads of Qout/KV; dense packed writes.
// ---------------------------------------------------------------------------
__global__ __launch_bounds__(256) void attn_kernel(
    const __half* __restrict__ Qout,   // [32768, 2048] cols: Qc | Qf(raw)
    const __half* __restrict__ KV,     // [65536, 4096] cols: Kc | Vc | Kf | Vf
    const float* __restrict__ S, const float* __restrict__ bqkv_conf,
    __half* __restrict__ AOc, __half* __restrict__ AOf)
{
    uint32_t gw = (blockIdx.x * blockDim.x + threadIdx.x) >> 5;
    int lane = threadIdx.x & 31;
    uint32_t branch = gw >> 19;
    uint32_t idx = gw & 0x7FFFFu;
    uint32_t b = idx >> 4, h = idx & 15;

    float2 q = ldcs_h2(Qout + (size_t)b * 2048 + branch * 1024 + h * 64 + 2 * lane);
    if (branch) {
        float s = 1.f + S[b];
        float2 qb = *(const float2*)(bqkv_conf + h * 64 + 2 * lane);
        q.x = fmaf(s, q.x, qb.x);
        q.y = fmaf(s, q.y, qb.y);
    }
    size_t kvb0 = (size_t)b * 4096 + branch * 2048 + h * 64 + 2 * lane;
    size_t kvb1 = (size_t)(32768 + b) * 4096 + branch * 2048 + h * 64 + 2 * lane;
    float2 k0 = ldcs_h2(KV + kvb0);
    float2 k1 = ldcs_h2(KV + kvb1);
    float s0 = q.x * k0.x + q.y * k0.y;
    float s1 = q.x * k1.x + q.y * k1.y;
#pragma unroll
    for (int o = 16; o; o >>= 1) {
        s0 += __shfl_xor_sync(0xffffffffu, s0, o);
        s1 += __shfl_xor_sync(0xffffffffu, s1, o);
    }
    s0 *= 0.125f;
    s1 *= 0.125f;
    float mx = fmaxf(s0, s1);
    float e0 = expf(s0 - mx), e1 = expf(s1 - mx);
    float inv = 1.f / (e0 + e1);
    float a0 = e0 * inv, a1 = e1 * inv;
    float2 v0 = ldcs_h2(KV + kvb0 + 1024);
    float2 v1 = ldcs_h2(KV + kvb1 + 1024);
    float ox = a0 * v0.x + a1 * v1.x;
    float oy = a0 * v0.y + a1 * v1.y;

    __half* AO = branch ? AOf : AOc;
    *(__half2*)(AO + packA_idx_h(b, h * 64 + 2 * lane)) = __floats2half2_rn(ox, oy);
}

// ---------------------------------------------------------------------------
// LayerNorm (both branches): warp per row; streaming fp16 in, packed fp16 out.
// ---------------------------------------------------------------------------
__global__ __launch_bounds__(256) void ln_kernel(
    const __half* __restrict__ X,
    const float* __restrict__ gamma, const float* __restrict__ beta,
    __half* __restrict__ Y)
{
    uint32_t row = (blockIdx.x * blockDim.x + threadIdx.x) >> 5;
    int lane = threadIdx.x & 31;
    const __half2* x2 = (const __half2*)(X + (size_t)row * 1024);
    float2 v[16];
    float s = 0.f, sq = 0.f;
#pragma unroll
    for (int i = 0; i < 16; ++i) {
        v[i] = __half22float2(__ldcs(x2 + lane + 32 * i));
        s += v[i].x + v[i].y;
        sq += v[i].x * v[i].x + v[i].y * v[i].y;
    }
#pragma unroll
    for (int o = 16; o; o >>= 1) {
        s  += __shfl_xor_sync(0xffffffffu, s, o);
        sq += __shfl_xor_sync(0xffffffffu, sq, o);
    }
    float mean = s * (1.f / 1024.f);
    float var  = sq * (1.f / 1024.f) - mean * mean;
    float rr = rsqrtf(var + 1e-5f);
#pragma unroll
    for (int i = 0; i < 16; ++i) {
        int d = 2 * (lane + 32 * i);
        float2 gm = *(const float2*)(gamma + d);
        float2 bt = *(const float2*)(beta + d);
        float y0 = (v[i].x - mean) * rr * gm.x + bt.x;
        float y1 = (v[i].y - mean) * rr * gm.y + bt.y;
        *(__half2*)(Y + packA_idx_h(row, (uint32_t)d)) = __floats2half2_rn(y0, y1);
    }
}

// ---------------------------------------------------------------------------
// Launch: R15 structure + forked stream for off-critical-path Wo/Wp packs.
// ---------------------------------------------------------------------------
extern "C" void kernel_launch(void* const* d_in, const int* in_sizes, int n_in,
                              void* d_out, int out_size)
{
    const float* Z_T       = (const float*)d_in[0];
    const float* Z_V       = (const float*)d_in[1];
    const float* Z_A       = (const float*)d_in[2];
    const float* S         = (const float*)d_in[3];
    const float* Wqkv_cons = (const float*)d_in[4];
    const float* bqkv_cons = (const float*)d_in[5];
    const float* Wo_cons   = (const float*)d_in[6];
    const float* bo_cons   = (const float*)d_in[7];
    const float* Wqkv_conf = (const float*)d_in[8];
    const float* bqkv_conf = (const float*)d_in[9];
    const float* Wo_conf   = (const float*)d_in[10];
    const float* bo_conf   = (const float*)d_in[11];
    const float* Wp_cons   = (const float*)d_in[12];
    const float* bp_cons   = (const float*)d_in[13];
    const float* Wp_conf   = (const float*)d_in[14];
    const float* bp_conf   = (const float*)d_in[15];
    const float* gamma     = (const float*)d_in[16];
    const float* beta      = (const float*)d_in[17];
    float* out = (float*)d_out;

    void* pp = nullptr; cudaGetSymbolAddress(&pp, g_pool);
    void* wp = nullptr; cudaGetSymbolAddress(&wp, g_wr);
    __half* hbase = (__half*)pp;
    __half* wh    = (__half*)wp;
    float*  wrf   = (float*)wp;

    float* biasQ  = wrf + 5ull * DD;       // 2048
    float* biasKV = biasQ + 2048;          // 4096
    float* biasO  = biasKV + 4096;         // 2048
    float* biasP  = biasO + 2048;          // 2048

    auto H  = [&](unsigned long long off) { return hbase + off; };
    auto H4 = [&](unsigned long long off) { return (const uint4*)(hbase + off); };
    auto W4 = [&](unsigned long long dd) { return (const uint4*)(wh + dd * DD); };
    const int WSEL = (int)(DD / 8);

    // One-time side-stream setup (resource caching only; identical work per call)
    static cudaStream_t s2 = nullptr;
    static cudaEvent_t evF = nullptr, evJ = nullptr;
    if (s2 == nullptr) {
        cudaStreamCreateWithFlags(&s2, cudaStreamNonBlocking);
        cudaEventCreateWithFlags(&evF, cudaEventDisableTiming);
        cudaEventCreateWithFlags(&evJ, cudaEventDisableTiming);
    }

    cudaFuncSetAttribute(gemm_qkv,                 cudaFuncAttributeMaxDynamicSharedMemorySize, SMEM_GEMM);
    cudaFuncSetAttribute(gemm_fp16<false, __half>, cudaFuncAttributeMaxDynamicSharedMemorySize, SMEM_GEMM);
    cudaFuncSetAttribute(gemm_fp16<true,  float>,  cudaFuncAttributeMaxDynamicSharedMemorySize, SMEM_GEMM);

    // Packs on the main stream (all QKV dependencies)
    pack_a<<<8192, 256>>>(Z_V, H(OFF_ZVA));
    pack_a<<<8192, 256>>>(Z_A, H(OFF_ZVA) + SLOT_ELEMS);
    pack_a<<<8192, 256>>>(Z_T, H(OFF_ZT));
    pack_w<<<512, 256>>>(Wqkv_cons + DD, wh + 2ull * DD);         // Wk_c, Wv_c
    pack_w<<<512, 256>>>(Wqkv_conf + DD, wh + 4ull * DD);         // Wk_f, Wv_f
    pack_w<<<256, 256>>>(Wqkv_cons, wh + 0ull * DD);              // Wq_c
    pack_w<<<256, 256>>>(Wqkv_conf, wh + 1ull * DD);              // Wq_f
    build_bias<<<16, 256>>>(bqkv_cons, bqkv_conf, bo_cons, bo_conf, bp_cons, bp_conf,
                            biasQ, biasKV, biasO, biasP);

    // Fork: Wo/Wp weight packs run on s2, overlapping gemm_qkv + attn
    cudaEventRecord(evF, 0);
    cudaStreamWaitEvent(s2, evF, 0);
    pack_w<<<256, 256, 0, s2>>>(Wo_cons, wh + 6ull * DD);
    pack_w<<<256, 256, 0, s2>>>(Wo_conf, wh + 7ull * DD);
    pack_w<<<256, 256, 0, s2>>>(Wp_cons, wh + 8ull * DD);
    pack_w<<<256, 256, 0, s2>>>(Wp_conf, wh + 9ull * DD);
    cudaEventRecord(evJ, s2);

    // Fused Q + KV GEMM: 16384 KV tiles + 4096 Q tiles in one launch
    gemm_qkv<<<20480, 256, SMEM_GEMM>>>(
        H4(OFF_ZT),  W4(0), biasQ,  H(OFF_QOUT),
        H4(OFF_ZVA), W4(2), biasKV, H(OFF_KV));

    // Attention
    attn_kernel<<<131072, 256>>>(H(OFF_QOUT), H(OFF_KV), S, bqkv_conf, H(OFF_AOC), H(OFF_AOF));

    // Join before consuming Wo/Wp packed weights
    cudaStreamWaitEvent(0, evJ, 0);

    // Output projection (both branches): [65536, 1024]
    gemm_fp16<false, __half><<<dim3(8, 512), 256, SMEM_GEMM>>>(
        H4(OFF_AOC), W4(6), biasO, H(OFF_C), 1024, WSEL, 1024);

    // LayerNorm (both branches)
    ln_kernel<<<8192, 256>>>(H(OFF_C), gamma, beta, H(OFF_LN));

    // Final projection + GELU: [65536, 1024] into d_out
    gemm_fp16<true, float><<<dim3(8, 512), 256, SMEM_GEMM>>>(
        H4(OFF_LN), W4(8), biasP, out, 1024, WSEL, 1024);
}